// round 5
// baseline (speedup 1.0000x reference)
#include <cuda_runtime.h>
#include <cstdint>

// SoftPixelCNN R5: one vertex per warp, 2 features per lane -> 18 accumulator
// regs, capped at 51 regs/thread for 40-warp/SM occupancy (latency-bound fix).
// Lane k computes the 9 offset weights for neighbor k in phase 1 (SMEM staged);
// phase 2 sweeps all K=32 with the full warp, each lane owning features
// {2*lane, 2*lane+1}. Offsets 0-7 accumulate as (o,o+1) f32x2 pairs fed by
// LDS.128 weight rows; offset 8 accumulates feature-paired, consuming the
// LDG.64 (f0,f1) pair directly.

typedef unsigned long long u64;

__global__ __launch_bounds__(256, 5)
void spcnn_kernel(const float* __restrict__ coords,   // (V,4)
                  const float* __restrict__ feats,    // (V,64)
                  const int*   __restrict__ nbr,      // (V,32)
                  const float* __restrict__ ls,       // (1,)
                  float*       __restrict__ out,      // (V,576)
                  int V)
{
    const int warp = threadIdx.x >> 5;
    const int lane = threadIdx.x & 31;
    const int v    = blockIdx.x * 8 + warp;

    struct WarpScratch {
        float w07[32][8];   // 1024 B: w0..w7 per k
        float w8a[32];      // 128 B : w8 per k
        int   ib [32];      // 128 B : neighbor indices
    };
    __shared__ __align__(16) WarpScratch ws[8];
    WarpScratch& S = ws[warp];

    if (v >= V) return;
    const float g = 10.0f * ls[0];

    // ---------------- Phase 1: lane k -> 9 weights for neighbor k --------------
    {
        const int idx = nbr[v * 32 + lane];
        const float4 cv = ((const float4*)coords)[v];
        const float4 cn = ((const float4*)coords)[idx];
        const float dx = cv.x - cn.x;
        const float dy = cv.y - cn.y;
        const float dz = cv.z - cn.z;
        const float dw = cv.w - cn.w;
        const float base = dx*dx + dy*dy + dz*dz + dw*dw;
        const float b1 = base + 1.0f;

        // OFFSETS (verified R1): o0=0 o1=-y o2=-x o3=-z o4=-w o5=+w o6=+z o7=+x o8=+y
        const float w0 = __expf(-g * base);
        const float w1 = __expf(-g * (b1 - 2.0f * dy));
        const float w2 = __expf(-g * (b1 - 2.0f * dx));
        const float w3 = __expf(-g * (b1 - 2.0f * dz));
        const float w4 = __expf(-g * (b1 - 2.0f * dw));
        const float w5 = __expf(-g * (b1 + 2.0f * dw));
        const float w6 = __expf(-g * (b1 + 2.0f * dz));
        const float w7 = __expf(-g * (b1 + 2.0f * dx));
        const float w8 = __expf(-g * (b1 + 2.0f * dy));

        float* wr = S.w07[lane];
        ((float4*)wr)[0] = make_float4(w0, w1, w2, w3);
        ((float4*)wr)[1] = make_float4(w4, w5, w6, w7);
        S.w8a[lane] = w8;
        S.ib [lane] = idx;
    }
    __syncwarp();

    // ---------------- Phase 2: full-warp sweep over K=32 ------------------------
    // accp[op][j]: offsets (2op,2op+1), feature j (j=0 -> 2*lane, j=1 -> 2*lane+1)
    // acc8p     : offset 8, feature pair (f0,f1)
    u64 accp[4][2];
    u64 acc8p = 0ull;
    #pragma unroll
    for (int op = 0; op < 4; ++op) { accp[op][0] = 0ull; accp[op][1] = 0ull; }

    const float* fcol = feats + lane * 2;

    #pragma unroll
    for (int gq = 0; gq < 8; ++gq) {
        const int4   i4  = *(const int4*)  &S.ib [gq * 4];
        const float4 w8v = *(const float4*)&S.w8a[gq * 4];
        const int   ns[4]  = { i4.x, i4.y, i4.z, i4.w };
        const float w8s[4] = { w8v.x, w8v.y, w8v.z, w8v.w };

        #pragma unroll
        for (int t = 0; t < 4; ++t) {
            const int k = gq * 4 + t;
            const u64 fv = *(const u64*)(fcol + (size_t)ns[t] * 64);  // (f0,f1)

            const ulonglong2* wr = (const ulonglong2*)S.w07[k];
            const ulonglong2 wA = wr[0];   // (w0,w1),(w2,w3)
            const ulonglong2 wB = wr[1];   // (w4,w5),(w6,w7)

            float f0, f1;
            asm("mov.b64 {%0,%1}, %2;" : "=f"(f0), "=f"(f1) : "l"(fv));
            u64 fp0, fp1, w8p;
            asm("mov.b64 %0, {%1,%1};" : "=l"(fp0) : "f"(f0));
            asm("mov.b64 %0, {%1,%1};" : "=l"(fp1) : "f"(f1));
            asm("mov.b64 %0, {%1,%1};" : "=l"(w8p) : "f"(w8s[t]));

            asm("fma.rn.f32x2 %0, %1, %2, %0;" : "+l"(accp[0][0]) : "l"(wA.x), "l"(fp0));
            asm("fma.rn.f32x2 %0, %1, %2, %0;" : "+l"(accp[0][1]) : "l"(wA.x), "l"(fp1));
            asm("fma.rn.f32x2 %0, %1, %2, %0;" : "+l"(accp[1][0]) : "l"(wA.y), "l"(fp0));
            asm("fma.rn.f32x2 %0, %1, %2, %0;" : "+l"(accp[1][1]) : "l"(wA.y), "l"(fp1));
            asm("fma.rn.f32x2 %0, %1, %2, %0;" : "+l"(accp[2][0]) : "l"(wB.x), "l"(fp0));
            asm("fma.rn.f32x2 %0, %1, %2, %0;" : "+l"(accp[2][1]) : "l"(wB.x), "l"(fp1));
            asm("fma.rn.f32x2 %0, %1, %2, %0;" : "+l"(accp[3][0]) : "l"(wB.y), "l"(fp0));
            asm("fma.rn.f32x2 %0, %1, %2, %0;" : "+l"(accp[3][1]) : "l"(wB.y), "l"(fp1));
            asm("fma.rn.f32x2 %0, %1, %2, %0;" : "+l"(acc8p)      : "l"(w8p),  "l"(fv));
        }
    }

    // ---------------- Epilogue: scale by 1/K, de-interleave, store --------------
    const u64 inv32p = 0x3D0000003D000000ull;   // (1/32, 1/32)
    float* orow = out + (size_t)v * 576 + lane * 2;

    #pragma unroll
    for (int op = 0; op < 4; ++op) {
        u64 m0 = accp[op][0], m1 = accp[op][1];
        asm("mul.rn.f32x2 %0, %0, %1;" : "+l"(m0) : "l"(inv32p));
        asm("mul.rn.f32x2 %0, %0, %1;" : "+l"(m1) : "l"(inv32p));
        const float2 e0 = *(float2*)&m0;   // (o=2op  : f0), (o=2op+1 : f0)
        const float2 e1 = *(float2*)&m1;   // (o=2op  : f1), (o=2op+1 : f1)
        *(float2*)(orow + (2 * op)     * 64) = make_float2(e0.x, e1.x);
        *(float2*)(orow + (2 * op + 1) * 64) = make_float2(e0.y, e1.y);
    }
    {
        u64 m8 = acc8p;
        asm("mul.rn.f32x2 %0, %0, %1;" : "+l"(m8) : "l"(inv32p));
        *(float2*)(orow + 8 * 64) = *(float2*)&m8;   // already (f0,f1)
    }
}

extern "C" void kernel_launch(void* const* d_in, const int* in_sizes, int n_in,
                              void* d_out, int out_size)
{
    const float* coords = (const float*)d_in[0];
    const float* feats  = (const float*)d_in[1];
    const int*   nbr    = (const int*)  d_in[3];
    const float* ls     = (const float*)d_in[4];
    float* out = (float*)d_out;

    const int V = in_sizes[0] / 4;
    const int blocks = (V + 7) / 8;   // one warp per vertex
    spcnn_kernel<<<blocks, 256>>>(coords, feats, nbr, ls, out, V);
}

// round 6
// speedup vs baseline: 1.1140x; 1.1140x over previous
#include <cuda_runtime.h>
#include <cstdint>

// SoftPixelCNN R6: R4 structure (2 vertices/warp via half-split, no merge)
// + explicit software pipeline: all 4 feature gathers of a k-group issued
// back-to-back (MLP=4) before the FMA block, and the next group's
// index/w8 LDS prefetched under the current group's FMAs.

typedef unsigned long long u64;

__global__ __launch_bounds__(128, 8)
void spcnn_kernel(const float* __restrict__ coords,   // (V,4)
                  const float* __restrict__ feats,    // (V,64)
                  const int*   __restrict__ nbr,      // (V,32)
                  const float* __restrict__ ls,       // (1,)
                  float*       __restrict__ out,      // (V,576)
                  int V)
{
    const int warp = threadIdx.x >> 5;
    const int lane = threadIdx.x & 31;
    const int hb   = lane >> 4;          // which vertex this half owns
    const int hl   = lane & 15;
    const int vbase = (blockIdx.x * 4 + warp) * 2;

    struct WarpScratch {
        float w07[2][32][8];   // 2048 B: weights w0..w7 per (vertex, k)
        float w8a[2][32];      // 256 B : w8 per (vertex, k)
        int   ib [2][32];      // 256 B : neighbor indices
    };
    __shared__ __align__(16) WarpScratch ws[4];
    WarpScratch& S = ws[warp];

    if (vbase >= V) return;
    const float g = 10.0f * ls[0];

    // ---------------- Phase 1: each lane fills weights for both vertices -------
    #pragma unroll
    for (int s = 0; s < 2; ++s) {
        const int v = vbase + s;
        if (v >= V) break;
        const int idx = nbr[v * 32 + lane];
        const float4 cv = ((const float4*)coords)[v];
        const float4 cn = ((const float4*)coords)[idx];
        const float dx = cv.x - cn.x;
        const float dy = cv.y - cn.y;
        const float dz = cv.z - cn.z;
        const float dw = cv.w - cn.w;
        const float base = dx*dx + dy*dy + dz*dz + dw*dw;
        const float b1 = base + 1.0f;

        // OFFSETS (verified R1): o0=0 o1=-y o2=-x o3=-z o4=-w o5=+w o6=+z o7=+x o8=+y
        const float w0 = __expf(-g * base);
        const float w1 = __expf(-g * (b1 - 2.0f * dy));
        const float w2 = __expf(-g * (b1 - 2.0f * dx));
        const float w3 = __expf(-g * (b1 - 2.0f * dz));
        const float w4 = __expf(-g * (b1 - 2.0f * dw));
        const float w5 = __expf(-g * (b1 + 2.0f * dw));
        const float w6 = __expf(-g * (b1 + 2.0f * dz));
        const float w7 = __expf(-g * (b1 + 2.0f * dx));
        const float w8 = __expf(-g * (b1 + 2.0f * dy));

        float* wr = S.w07[s][lane];
        ((float4*)wr)[0] = make_float4(w0, w1, w2, w3);
        ((float4*)wr)[1] = make_float4(w4, w5, w6, w7);
        S.w8a[s][lane] = w8;
        S.ib [s][lane] = idx;
    }
    __syncwarp();

    // ---------------- Phase 2: half-split sweep, software-pipelined -------------
    const int v = vbase + hb;
    if (v >= V) return;

    u64   accp[4][4];                    // (offset 2op, 2op+1) x feature j
    float acc8[4];
    #pragma unroll
    for (int op = 0; op < 4; ++op)
        #pragma unroll
        for (int j = 0; j < 4; ++j) accp[op][j] = 0ull;
    #pragma unroll
    for (int j = 0; j < 4; ++j) acc8[j] = 0.0f;

    const int fc = hl * 4;
    const float* fbase = feats + fc;

    // pipeline preload: group 0 metadata
    int4   i4  = *(const int4*)  &S.ib [hb][0];
    float4 w8v = *(const float4*)&S.w8a[hb][0];

    #pragma unroll
    for (int gq = 0; gq < 8; ++gq) {
        // 1) issue all 4 feature gathers back-to-back (MLP = 4)
        const float4 fv0 = *(const float4*)(fbase + (size_t)i4.x * 64);
        const float4 fv1 = *(const float4*)(fbase + (size_t)i4.y * 64);
        const float4 fv2 = *(const float4*)(fbase + (size_t)i4.z * 64);
        const float4 fv3 = *(const float4*)(fbase + (size_t)i4.w * 64);
        const float w8s[4] = { w8v.x, w8v.y, w8v.z, w8v.w };

        // 2) prefetch next group's metadata under this group's FMAs
        if (gq < 7) {
            i4  = *(const int4*)  &S.ib [hb][(gq + 1) * 4];
            w8v = *(const float4*)&S.w8a[hb][(gq + 1) * 4];
        }

        const float4 fvs[4] = { fv0, fv1, fv2, fv3 };

        // 3) consume
        #pragma unroll
        for (int t = 0; t < 4; ++t) {
            const int k = gq * 4 + t;
            const float4 fv = fvs[t];

            const ulonglong2* wr = (const ulonglong2*)S.w07[hb][k];
            const ulonglong2 wA = wr[0];   // (w0,w1),(w2,w3)
            const ulonglong2 wB = wr[1];   // (w4,w5),(w6,w7)

            u64 fp[4];
            asm("mov.b64 %0, {%1,%1};" : "=l"(fp[0]) : "f"(fv.x));
            asm("mov.b64 %0, {%1,%1};" : "=l"(fp[1]) : "f"(fv.y));
            asm("mov.b64 %0, {%1,%1};" : "=l"(fp[2]) : "f"(fv.z));
            asm("mov.b64 %0, {%1,%1};" : "=l"(fp[3]) : "f"(fv.w));

            #pragma unroll
            for (int j = 0; j < 4; ++j) {
                asm("fma.rn.f32x2 %0, %1, %2, %0;" : "+l"(accp[0][j]) : "l"(wA.x), "l"(fp[j]));
                asm("fma.rn.f32x2 %0, %1, %2, %0;" : "+l"(accp[1][j]) : "l"(wA.y), "l"(fp[j]));
                asm("fma.rn.f32x2 %0, %1, %2, %0;" : "+l"(accp[2][j]) : "l"(wB.x), "l"(fp[j]));
                asm("fma.rn.f32x2 %0, %1, %2, %0;" : "+l"(accp[3][j]) : "l"(wB.y), "l"(fp[j]));
            }
            acc8[0] = fmaf(w8s[t], fv.x, acc8[0]);
            acc8[1] = fmaf(w8s[t], fv.y, acc8[1]);
            acc8[2] = fmaf(w8s[t], fv.z, acc8[2]);
            acc8[3] = fmaf(w8s[t], fv.w, acc8[3]);
        }
    }

    // ---------------- Epilogue: scale by 1/K, de-interleave, store --------------
    const u64   inv32p = 0x3D0000003D000000ull;   // (1/32, 1/32)
    const float inv32  = 0.03125f;
    float* orow = out + (size_t)v * 576 + fc;

    #pragma unroll
    for (int op = 0; op < 4; ++op) {
        #pragma unroll
        for (int j = 0; j < 4; ++j)
            asm("mul.rn.f32x2 %0, %0, %1;" : "+l"(accp[op][j]) : "l"(inv32p));
        const float2 e0 = *(float2*)&accp[op][0];
        const float2 e1 = *(float2*)&accp[op][1];
        const float2 e2 = *(float2*)&accp[op][2];
        const float2 e3 = *(float2*)&accp[op][3];
        *(float4*)(orow + (2 * op)     * 64) = make_float4(e0.x, e1.x, e2.x, e3.x);
        *(float4*)(orow + (2 * op + 1) * 64) = make_float4(e0.y, e1.y, e2.y, e3.y);
    }
    *(float4*)(orow + 8 * 64) = make_float4(acc8[0] * inv32, acc8[1] * inv32,
                                            acc8[2] * inv32, acc8[3] * inv32);
}

extern "C" void kernel_launch(void* const* d_in, const int* in_sizes, int n_in,
                              void* d_out, int out_size)
{
    const float* coords = (const float*)d_in[0];
    const float* feats  = (const float*)d_in[1];
    const int*   nbr    = (const int*)  d_in[3];
    const float* ls     = (const float*)d_in[4];
    float* out = (float*)d_out;

    const int V = in_sizes[0] / 4;
    const int verts_per_block = 8;    // 4 warps x 2 vertices
    const int blocks = (V + verts_per_block - 1) / verts_per_block;
    spcnn_kernel<<<blocks, 128>>>(coords, feats, nbr, ls, out, V);
}